// round 8
// baseline (speedup 1.0000x reference)
#include <cuda_runtime.h>

// VectorP1FunctionSpace: evaluate two P1 FEM interpolants (wx, wy) on a
// structured 32x32 triangulation of [0,1]^2 via the exact analytic barycentric
// form (the reference's relu/min hat construction == barycentric coords).
//
// R7: overhead/latency bound; float2-interleaved SMEM tables (R6) was a win.
// Now vectorize the table fill: float4 loads of both tables (272 chunks of 4
// vertices), interleave in registers, 2x STS.128 per chunk. Per-thread fill
// drops from ~18 LDG.32 + 9 STS.64 to ~2 LDG.128 + 2 STS.128, shortening the
// fill tail behind the barrier. Eval path unchanged.

#define NXY    32
#define NYP1   33
#define NVERT  1089        // 272*4 + 1
#define NCHUNK 272

__device__ __forceinline__ void eval_point(float px, float py,
                                           const float2* __restrict__ sw,
                                           float& ox, float& oy)
{
    float sx = px * (float)NXY;
    float sy = py * (float)NXY;

    int i = (int)floorf(sx);
    int j = (int)floorf(sy);
    i = min(max(i, 0), NXY - 1);
    j = min(max(j, 0), NXY - 1);

    float fx = sx - (float)i;
    float fy = sy - (float)j;

    int v00 = i * NYP1 + j;
    int v11 = v00 + NYP1 + 1;

    // lower-right tri (v00,v10,v11): (1-fx, fx-fy, fy); else (v00,v11,v01): (1-fy, fx, fy-fx)
    bool  lower = (fx >= fy);
    float fm    = lower ? fx : fy;
    int   vb    = lower ? (v00 + NYP1) : v11;
    int   vc    = lower ? v11 : (v00 + 1);
    float l0    = 1.0f - fm;
    float l1    = lower ? (fx - fy) : fx;
    float l2    = lower ? fy : (fy - fx);

    float2 wa = sw[v00];
    float2 wb = sw[vb];
    float2 wc = sw[vc];

    ox = fmaf(l0, wa.x, fmaf(l1, wb.x, l2 * wc.x));
    oy = fmaf(l0, wa.y, fmaf(l1, wb.y, l2 * wc.y));
}

__global__ __launch_bounds__(256, 1)
void vp1_eval_kernel(const float4* __restrict__ x,
                     const float*  __restrict__ wx,
                     const float*  __restrict__ wy,
                     float4*       __restrict__ out,
                     int npairs)
{
    __shared__ __align__(16) float2 sw[NVERT + 1];   // +1 pad keeps float4 stores in-bounds

    int tid = threadIdx.x;
    int idx = blockIdx.x * blockDim.x + tid;

    // 1) Dependent load first: two query points (16B). In flight during fill.
    float4 p;
    bool active = (idx < npairs);
    if (active) p = x[idx];

    // 2) Vectorized SMEM fill, interleaved (wx[v], wy[v]) -> sw[v].
    //    272 float4 chunks per table; 2x STS.128 per chunk.
    {
        const float4* wx4 = (const float4*)wx;
        const float4* wy4 = (const float4*)wy;
        float4* sw4 = (float4*)sw;
        #pragma unroll
        for (int c = tid; c < NCHUNK; c += 256) {
            float4 a = __ldg(&wx4[c]);
            float4 b = __ldg(&wy4[c]);
            sw4[2 * c]     = make_float4(a.x, b.x, a.y, b.y);
            sw4[2 * c + 1] = make_float4(a.z, b.z, a.w, b.w);
        }
        if (tid == 0)
            sw[NVERT - 1] = make_float2(__ldg(&wx[NVERT - 1]), __ldg(&wy[NVERT - 1]));
    }
    __syncthreads();

    if (!active) return;

    float4 r;
    eval_point(p.x, p.y, sw, r.x, r.y);
    eval_point(p.z, p.w, sw, r.z, r.w);

    out[idx] = r;
}

extern "C" void kernel_launch(void* const* d_in, const int* in_sizes, int n_in,
                              void* d_out, int out_size)
{
    const float* x  = (const float*)d_in[0];   // [B, N, 2]
    // d_in[1] = W [V,6,2], d_in[2] = c [V,6]  -- unused (analytic form)
    const float* wx = (const float*)d_in[3];   // [V]
    const float* wy = (const float*)d_in[4];   // [V]
    float* out = (float*)d_out;                // [B, N, 2]

    int npairs = out_size / 4;                 // 2 points (4 floats) per thread

    int threads = 256;
    int blocks  = (npairs + threads - 1) / threads;   // 32 CTAs for 8192 pairs
    vp1_eval_kernel<<<blocks, threads>>>((const float4*)x, wx, wy,
                                         (float4*)out, npairs);
}